// round 7
// baseline (speedup 1.0000x reference)
#include <cuda_runtime.h>

// NodeModel GNN: two (Linear -> BN(train) -> ReLU -> Linear) stages with a
// scatter-mean between them. N=50000, E=800000, FX=H=64.
// Concat-GEMMs split:  [x[s],ea]@W = (x@W_top)[s] + ea@W_bot.

static __device__ float g_h1 [800000 * 64];   // edge hidden (pre-BN)
static __device__ float g_h1n[ 50048 * 64];   // node hidden (pre-BN)
static __device__ float g_xwm[ 50048 * 64];   // x @ w1m_top
static __device__ float g_xwn[ 50048 * 64];   // x @ w1n_top
static __device__ float g_agg[ 50048 * 64];   // scatter sums
static __device__ float g_cnt[ 50048];        // scatter counts
static __device__ float g_stat[8][64];        // {sum,ssq,scale,shift} x {m,n}

__device__ __forceinline__ float2 up2(unsigned long long p) {
    float2 r;
    asm("mov.b64 {%0, %1}, %2;" : "=f"(r.x), "=f"(r.y) : "l"(p));
    return r;
}
__device__ __forceinline__ unsigned long long dup2(float a) {
    unsigned long long r; unsigned int u = __float_as_uint(a);
    asm("mov.b64 %0, {%1, %1};" : "=l"(r) : "r"(u));
    return r;
}
#define FMA2(acc, a, w) \
    asm("fma.rn.f32x2 %0, %1, %2, %0;" : "+l"(acc) : "l"(a), "l"(w))

__device__ __forceinline__ void fill_W(float* Ws, const float* __restrict__ Wg,
                                       int tid) {
#pragma unroll
    for (int it = 0; it < 16; ++it) Ws[tid + it * 256] = __ldg(Wg + tid + it * 256);
}

// C[128x64] = A[128x64] @ W[64x64]; A XOR-swizzled at float4 granularity.
__device__ __forceinline__ void gemm_core(const float* __restrict__ A_s,
                                          const float* __restrict__ W_s,
                                          unsigned long long acc[4][4],
                                          int tr, int tc) {
#pragma unroll
    for (int k4 = 0; k4 < 16; ++k4) {
        float4 a[4];
#pragma unroll
        for (int i = 0; i < 4; ++i) {
            const int r = i * 32 + tr;
            a[i] = *(const float4*)(A_s + r * 64 + ((k4 ^ (r & 3)) << 2));
        }
#pragma unroll
        for (int kk = 0; kk < 4; ++kk) {
            const int k = k4 * 4 + kk;
            const ulonglong2 w0 = *(const ulonglong2*)(W_s + k * 64 + tc * 8);
            const ulonglong2 w1 = *(const ulonglong2*)(W_s + k * 64 + tc * 8 + 4);
#pragma unroll
            for (int i = 0; i < 4; ++i) {
                const unsigned long long a2 = dup2(((const float*)&a[i])[kk]);
                FMA2(acc[i][0], a2, w0.x);
                FMA2(acc[i][1], a2, w0.y);
                FMA2(acc[i][2], a2, w1.x);
                FMA2(acc[i][3], a2, w1.y);
            }
        }
    }
}

__global__ void k_zero(int n64, int n) {
    const int i = blockIdx.x * 256 + threadIdx.x;
    if (i < n64) g_agg[i] = 0.f;
    if (i < n)   g_cnt[i] = 0.f;
    if (i < 512) ((float*)g_stat)[i] = 0.f;
}

// xw(which) = X @ W_top (rows 0..63 of W)
__global__ __launch_bounds__(256, 2)
void k_rowgemm(const float* __restrict__ X, const float* __restrict__ Wg,
               int nrows, int which) {
    __shared__ __align__(16) float A_s[128 * 64];
    __shared__ __align__(16) float W_s[64 * 64];
    const int tid = threadIdx.x, r0 = blockIdx.x * 128;
    fill_W(W_s, Wg, tid);
    {
        const int c4 = tid & 15, rb = tid >> 4;
#pragma unroll
        for (int it = 0; it < 8; ++it) {
            const int r = rb + it * 16, n = r0 + r;
            float4 v = make_float4(0.f, 0.f, 0.f, 0.f);
            if (n < nrows) v = __ldg((const float4*)(X + (size_t)n * 64 + c4 * 4));
            *(float4*)(A_s + r * 64 + ((c4 ^ (r & 3)) << 2)) = v;
        }
    }
    __syncthreads();
    const int tc = tid & 7, tr = tid >> 3;
    unsigned long long acc[4][4] = {};
    gemm_core(A_s, W_s, acc, tr, tc);
    float* outp = which ? g_xwn : g_xwm;
#pragma unroll
    for (int i = 0; i < 4; ++i) {
        const int n = r0 + i * 32 + tr;
        if (n < nrows) {
            float2 p0 = up2(acc[i][0]), p1 = up2(acc[i][1]);
            float2 p2 = up2(acc[i][2]), p3 = up2(acc[i][3]);
            *(float4*)(outp + (size_t)n * 64 + tc * 8)     = make_float4(p0.x, p0.y, p1.x, p1.y);
            *(float4*)(outp + (size_t)n * 64 + tc * 8 + 4) = make_float4(p2.x, p2.y, p3.x, p3.y);
        }
    }
}

// stage0: h1[e]  = ea[e]@w_bot + xwm[send[e]] + b   (+ BN sum/ssq)
// stage1: h1n[n] = (agg[n]/max(cnt,1))@w_bot + xwn[n] + b
__global__ __launch_bounds__(256, 2)
void k_stage1(const float* __restrict__ Araw, const int* __restrict__ eidx,
              const float* __restrict__ Wbot, const float* __restrict__ bias,
              int nrows, int stage) {
    __shared__ __align__(16) float A_s[128 * 64];
    __shared__ __align__(16) float W_s[64 * 64];
    const int tid = threadIdx.x, r0 = blockIdx.x * 128;
    fill_W(W_s, Wbot, tid);
    {
        const int c4 = tid & 15, rb = tid >> 4;
#pragma unroll
        for (int it = 0; it < 8; ++it) {
            const int r = rb + it * 16, n = r0 + r;
            float4 v = make_float4(0.f, 0.f, 0.f, 0.f);
            if (n < nrows) {
                if (stage == 0) {
                    v = __ldg((const float4*)(Araw + (size_t)n * 64 + c4 * 4));
                } else {
                    const float is = 1.0f / fmaxf(g_cnt[n], 1.0f);
                    v = *(const float4*)(g_agg + (size_t)n * 64 + c4 * 4);
                    v.x *= is; v.y *= is; v.z *= is; v.w *= is;
                }
            }
            *(float4*)(A_s + r * 64 + ((c4 ^ (r & 3)) << 2)) = v;
        }
    }
    __syncthreads();
    const int tc = tid & 7, tr = tid >> 3;
    unsigned long long acc[4][4] = {};
    gemm_core(A_s, W_s, acc, tr, tc);

    const float4 bA = __ldg((const float4*)(bias + tc * 8));
    const float4 bB = __ldg((const float4*)(bias + tc * 8 + 4));
    const float* xw = stage ? g_xwn : g_xwm;
    float* hp = stage ? g_h1n : g_h1;
    float s_[8] = {}, q_[8] = {};
#pragma unroll
    for (int i = 0; i < 4; ++i) {
        const int n = r0 + i * 32 + tr;
        if (n < nrows) {
            const int s = stage ? n : __ldg(eidx + n);
            const float4 x0 = __ldg((const float4*)(xw + (size_t)s * 64 + tc * 8));
            const float4 x1 = __ldg((const float4*)(xw + (size_t)s * 64 + tc * 8 + 4));
            float2 p0 = up2(acc[i][0]), p1 = up2(acc[i][1]);
            float2 p2 = up2(acc[i][2]), p3 = up2(acc[i][3]);
            float v[8];
            v[0] = p0.x + x0.x + bA.x; v[1] = p0.y + x0.y + bA.y;
            v[2] = p1.x + x0.z + bA.z; v[3] = p1.y + x0.w + bA.w;
            v[4] = p2.x + x1.x + bB.x; v[5] = p2.y + x1.y + bB.y;
            v[6] = p3.x + x1.z + bB.z; v[7] = p3.y + x1.w + bB.w;
            *(float4*)(hp + (size_t)n * 64 + tc * 8)     = make_float4(v[0], v[1], v[2], v[3]);
            *(float4*)(hp + (size_t)n * 64 + tc * 8 + 4) = make_float4(v[4], v[5], v[6], v[7]);
#pragma unroll
            for (int j = 0; j < 8; ++j) { s_[j] += v[j]; q_[j] += v[j] * v[j]; }
        }
    }
#pragma unroll
    for (int j = 0; j < 8; ++j) {
        s_[j] += __shfl_xor_sync(0xffffffffu, s_[j], 8);
        s_[j] += __shfl_xor_sync(0xffffffffu, s_[j], 16);
        q_[j] += __shfl_xor_sync(0xffffffffu, q_[j], 8);
        q_[j] += __shfl_xor_sync(0xffffffffu, q_[j], 16);
    }
    __syncthreads();                  // reuse A_s for block reduction
    if (tid < 128) A_s[tid] = 0.f;
    __syncthreads();
    if ((tid & 31) < 8) {
#pragma unroll
        for (int j = 0; j < 8; ++j) {
            atomicAdd(&A_s[tc * 8 + j], s_[j]);
            atomicAdd(&A_s[64 + tc * 8 + j], q_[j]);
        }
    }
    __syncthreads();
    if (tid < 64) {
        atomicAdd(&g_stat[stage * 4 + 0][tid], A_s[tid]);
        atomicAdd(&g_stat[stage * 4 + 1][tid], A_s[64 + tid]);
    }
}

__global__ void k_bnfin(const float* __restrict__ gamma,
                        const float* __restrict__ beta, float invcnt, int stage) {
    const int c = threadIdx.x;
    const float mu = g_stat[stage * 4 + 0][c] * invcnt;
    const float var = g_stat[stage * 4 + 1][c] * invcnt - mu * mu;
    const float sc = __ldg(gamma + c) * rsqrtf(var + 1e-5f);
    g_stat[stage * 4 + 2][c] = sc;
    g_stat[stage * 4 + 3][c] = __ldg(beta + c) - mu * sc;
}

// stage0: m = relu(bn(h1)) @ w2m + b2m -> red.v4 scatter into g_agg, count g_cnt
// stage1: out = relu(bn(h1n)) @ w2n + b2n
__global__ __launch_bounds__(256, 2)
void k_stage2(const int* __restrict__ eidx, const float* __restrict__ Wg,
              const float* __restrict__ bias, int nrows, int stage,
              float* __restrict__ out) {
    __shared__ __align__(16) float A_s[128 * 64];
    __shared__ __align__(16) float W_s[64 * 64];
    const int tid = threadIdx.x, r0 = blockIdx.x * 128;
    if (stage == 0 && tid < 128) {
        const int e = r0 + tid;
        if (e < nrows) atomicAdd(&g_cnt[__ldg(eidx + nrows + e)], 1.0f);
    }
    fill_W(W_s, Wg, tid);
    {
        const int c4 = tid & 15, rb = tid >> 4;
        const float4 sc = *(const float4*)(&g_stat[stage * 4 + 2][c4 * 4]);
        const float4 sh = *(const float4*)(&g_stat[stage * 4 + 3][c4 * 4]);
        const float* hp = stage ? g_h1n : g_h1;
#pragma unroll
        for (int it = 0; it < 8; ++it) {
            const int r = rb + it * 16, n = r0 + r;
            float4 v = make_float4(0.f, 0.f, 0.f, 0.f);
            if (n < nrows) {
                v = *(const float4*)(hp + (size_t)n * 64 + c4 * 4);
                v.x = fmaxf(fmaf(v.x, sc.x, sh.x), 0.f);
                v.y = fmaxf(fmaf(v.y, sc.y, sh.y), 0.f);
                v.z = fmaxf(fmaf(v.z, sc.z, sh.z), 0.f);
                v.w = fmaxf(fmaf(v.w, sc.w, sh.w), 0.f);
            }
            *(float4*)(A_s + r * 64 + ((c4 ^ (r & 3)) << 2)) = v;
        }
    }
    __syncthreads();
    const int tc = tid & 7, tr = tid >> 3;
    unsigned long long acc[4][4] = {};
    gemm_core(A_s, W_s, acc, tr, tc);

    const float4 bA = __ldg((const float4*)(bias + tc * 8));
    const float4 bB = __ldg((const float4*)(bias + tc * 8 + 4));
#pragma unroll
    for (int i = 0; i < 4; ++i) {
        const int n = r0 + i * 32 + tr;
        if (n < nrows) {
            float2 p0 = up2(acc[i][0]), p1 = up2(acc[i][1]);
            float2 p2 = up2(acc[i][2]), p3 = up2(acc[i][3]);
            const float v0 = p0.x + bA.x, v1 = p0.y + bA.y;
            const float v2 = p1.x + bA.z, v3 = p1.y + bA.w;
            const float v4 = p2.x + bB.x, v5 = p2.y + bB.y;
            const float v6 = p3.x + bB.z, v7 = p3.y + bB.w;
            if (stage == 0) {
                const int rec = __ldg(eidx + nrows + n);
                float* p = g_agg + (size_t)rec * 64 + tc * 8;
                asm volatile("red.global.add.v4.f32 [%0], {%1,%2,%3,%4};"
                             :: "l"(p), "f"(v0), "f"(v1), "f"(v2), "f"(v3));
                asm volatile("red.global.add.v4.f32 [%0], {%1,%2,%3,%4};"
                             :: "l"(p + 4), "f"(v4), "f"(v5), "f"(v6), "f"(v7));
            } else {
                *(float4*)(out + (size_t)n * 64 + tc * 8)     = make_float4(v0, v1, v2, v3);
                *(float4*)(out + (size_t)n * 64 + tc * 8 + 4) = make_float4(v4, v5, v6, v7);
            }
        }
    }
}

extern "C" void kernel_launch(void* const* d_in, const int* in_sizes, int n_in,
                              void* d_out, int out_size) {
    const float* x    = (const float*)d_in[0];
    const int*   eidx = (const int*)  d_in[1];
    const float* ea   = (const float*)d_in[2];
    const float* w1m  = (const float*)d_in[5];
    const float* b1m  = (const float*)d_in[6];
    const float* gm   = (const float*)d_in[7];
    const float* bm   = (const float*)d_in[8];
    const float* w2m  = (const float*)d_in[9];
    const float* b2m  = (const float*)d_in[10];
    const float* w1n  = (const float*)d_in[11];
    const float* b1n  = (const float*)d_in[12];
    const float* gn   = (const float*)d_in[13];
    const float* bn   = (const float*)d_in[14];
    const float* w2n  = (const float*)d_in[15];
    const float* b2n  = (const float*)d_in[16];
    const int N = in_sizes[0] / 64;
    const int E = in_sizes[2] / 64;
    const int gN = (N + 127) / 128, gE = (E + 127) / 128;

    k_zero<<<(N * 64 + 255) / 256, 256>>>(N * 64, N);
    k_rowgemm<<<gN, 256>>>(x, w1m, N, 0);
    k_rowgemm<<<gN, 256>>>(x, w1n, N, 1);
    k_stage1<<<gE, 256>>>(ea, eidx, w1m + 4096, b1m, E, 0);
    k_bnfin<<<1, 64>>>(gm, bm, 1.0f / (float)E, 0);
    k_stage2<<<gE, 256>>>(eidx, w2m, b2m, E, 0, nullptr);
    k_stage1<<<gN, 256>>>(nullptr, nullptr, w1n + 4096, b1n, N, 1);
    k_bnfin<<<1, 64>>>(gn, bn, 1.0f / (float)N, 1);
    k_stage2<<<gN, 256>>>(nullptr, w2n, b2n, N, 1, (float*)d_out);
}

// round 8
// speedup vs baseline: 1.1560x; 1.1560x over previous
#include <cuda_runtime.h>

// NodeModel GNN: two (Linear -> BN(train) -> ReLU -> Linear) stages with a
// scatter-mean between them. N=50000, E=800000, FX=H=64.
// Concat-GEMMs split:  [x[s],ea]@W = (x@W_top)[s] + ea@W_bot.
// Edge-side kernels are persistent (2 blocks/SM) with cp.async double buffering.

static __device__ float g_h1 [800000 * 64];   // edge hidden (pre-BN)
static __device__ float g_h1n[ 50048 * 64];   // node hidden (pre-BN)
static __device__ float g_xwm[ 50048 * 64];   // x @ w1m_top
static __device__ float g_xwn[ 50048 * 64];   // x @ w1n_top
static __device__ float g_agg[ 50048 * 64];   // scatter sums
static __device__ float g_cnt[ 50048];        // scatter counts
static __device__ float g_stat[8][64];        // {sum,ssq,scale,shift} x {m,n}

__device__ __forceinline__ float2 up2(unsigned long long p) {
    float2 r;
    asm("mov.b64 {%0, %1}, %2;" : "=f"(r.x), "=f"(r.y) : "l"(p));
    return r;
}
__device__ __forceinline__ unsigned long long dup2(float a) {
    unsigned long long r; unsigned int u = __float_as_uint(a);
    asm("mov.b64 %0, {%1, %1};" : "=l"(r) : "r"(u));
    return r;
}
#define FMA2(acc, a, w) \
    asm("fma.rn.f32x2 %0, %1, %2, %0;" : "+l"(acc) : "l"(a), "l"(w))

__device__ __forceinline__ void cp16(float* dst, const float* src, int sz) {
    unsigned d = (unsigned)__cvta_generic_to_shared(dst);
    asm volatile("cp.async.cg.shared.global [%0], [%1], 16, %2;"
                 :: "r"(d), "l"(src), "r"(sz));
}
#define CP_COMMIT() asm volatile("cp.async.commit_group;")
#define CP_WAIT1()  asm volatile("cp.async.wait_group 1;")

__device__ __forceinline__ void fill_W(float* Ws, const float* __restrict__ Wg,
                                       int tid) {
#pragma unroll
    for (int it = 0; it < 16; ++it) Ws[tid + it * 256] = __ldg(Wg + tid + it * 256);
}

// C[128x64] = A[128x64] @ W[64x64]; A XOR-swizzled at float4 granularity.
__device__ __forceinline__ void gemm_core(const float* __restrict__ A_s,
                                          const float* __restrict__ W_s,
                                          unsigned long long acc[4][4],
                                          int tr, int tc) {
#pragma unroll
    for (int k4 = 0; k4 < 16; ++k4) {
        float4 a[4];
#pragma unroll
        for (int i = 0; i < 4; ++i) {
            const int r = i * 32 + tr;
            a[i] = *(const float4*)(A_s + r * 64 + ((k4 ^ (r & 3)) << 2));
        }
#pragma unroll
        for (int kk = 0; kk < 4; ++kk) {
            const int k = k4 * 4 + kk;
            const ulonglong2 w0 = *(const ulonglong2*)(W_s + k * 64 + tc * 8);
            const ulonglong2 w1 = *(const ulonglong2*)(W_s + k * 64 + tc * 8 + 4);
#pragma unroll
            for (int i = 0; i < 4; ++i) {
                const unsigned long long a2 = dup2(((const float*)&a[i])[kk]);
                FMA2(acc[i][0], a2, w0.x);
                FMA2(acc[i][1], a2, w0.y);
                FMA2(acc[i][2], a2, w1.x);
                FMA2(acc[i][3], a2, w1.y);
            }
        }
    }
}

__global__ void k_zero(int n64, int n) {
    const int i = blockIdx.x * 256 + threadIdx.x;
    if (i < n64) g_agg[i] = 0.f;
    if (i < n)   g_cnt[i] = 0.f;
    if (i < 512) ((float*)g_stat)[i] = 0.f;
}

// xw = X @ W_top; blockIdx.y selects (w1m -> g_xwm) / (w1n -> g_xwn)
__global__ __launch_bounds__(256, 2)
void k_rowgemm(const float* __restrict__ X, const float* __restrict__ Wm,
               const float* __restrict__ Wn, int nrows) {
    __shared__ __align__(16) float A_s[128 * 64];
    __shared__ __align__(16) float W_s[64 * 64];
    const int tid = threadIdx.x, r0 = blockIdx.x * 128;
    fill_W(W_s, blockIdx.y ? Wn : Wm, tid);
    {
        const int c4 = tid & 15, rb = tid >> 4;
#pragma unroll
        for (int it = 0; it < 8; ++it) {
            const int r = rb + it * 16, n = r0 + r;
            float4 v = make_float4(0.f, 0.f, 0.f, 0.f);
            if (n < nrows) v = __ldg((const float4*)(X + (size_t)n * 64 + c4 * 4));
            *(float4*)(A_s + r * 64 + ((c4 ^ (r & 3)) << 2)) = v;
        }
    }
    __syncthreads();
    const int tc = tid & 7, tr = tid >> 3;
    unsigned long long acc[4][4] = {};
    gemm_core(A_s, W_s, acc, tr, tc);
    float* outp = blockIdx.y ? g_xwn : g_xwm;
#pragma unroll
    for (int i = 0; i < 4; ++i) {
        const int n = r0 + i * 32 + tr;
        if (n < nrows) {
            float2 p0 = up2(acc[i][0]), p1 = up2(acc[i][1]);
            float2 p2 = up2(acc[i][2]), p3 = up2(acc[i][3]);
            *(float4*)(outp + (size_t)n * 64 + tc * 8)     = make_float4(p0.x, p0.y, p1.x, p1.y);
            *(float4*)(outp + (size_t)n * 64 + tc * 8 + 4) = make_float4(p2.x, p2.y, p3.x, p3.y);
        }
    }
}

// Persistent: h1[e] = ea[e]@Wbot + xwm[send[e]] + b, BN stats, + degree count.
__global__ __launch_bounds__(256, 2)
void k_edge1(const float* __restrict__ ea, const int* __restrict__ eidx,
             const float* __restrict__ Wbot, const float* __restrict__ bias,
             int E, int ntiles) {
    __shared__ __align__(16) float A_s[2][128 * 64];
    __shared__ __align__(16) float W_s[64 * 64];
    const int tid = threadIdx.x;
    const int tc = tid & 7, tr = tid >> 3;
    const int c4 = tid & 15, rb = tid >> 4;
    fill_W(W_s, Wbot, tid);
    const float4 bA = __ldg((const float4*)(bias + tc * 8));
    const float4 bB = __ldg((const float4*)(bias + tc * 8 + 4));
    float s_[8] = {}, q_[8] = {};

    int t = blockIdx.x;
    if (t < ntiles) {
        const int r0 = t * 128;
#pragma unroll
        for (int it = 0; it < 8; ++it) {
            const int r = rb + it * 16, e = r0 + r;
            cp16(A_s[0] + r * 64 + ((c4 ^ (r & 3)) << 2),
                 ea + (size_t)e * 64 + c4 * 4, e < E ? 16 : 0);
        }
    }
    CP_COMMIT();
    int buf = 0;
    for (; t < ntiles; t += gridDim.x) {
        const int tn = t + gridDim.x;
        if (tn < ntiles) {
            const int r0n = tn * 128;
#pragma unroll
            for (int it = 0; it < 8; ++it) {
                const int r = rb + it * 16, e = r0n + r;
                cp16(A_s[buf ^ 1] + r * 64 + ((c4 ^ (r & 3)) << 2),
                     ea + (size_t)e * 64 + c4 * 4, e < E ? 16 : 0);
            }
        }
        CP_COMMIT();
        const int r0 = t * 128;
        int snd[4], rec[4];
#pragma unroll
        for (int i = 0; i < 4; ++i) {
            const int n = r0 + i * 32 + tr;
            snd[i] = (n < E) ? __ldg(eidx + n) : 0;
            rec[i] = (n < E) ? __ldg(eidx + E + n) : 0;
        }
        CP_WAIT1();
        __syncthreads();
        unsigned long long acc[4][4] = {};
        gemm_core(A_s[buf], W_s, acc, tr, tc);
#pragma unroll
        for (int i = 0; i < 4; ++i) {
            const int n = r0 + i * 32 + tr;
            if (n < E) {
                const float4 x0 = __ldg((const float4*)(g_xwm + (size_t)snd[i] * 64 + tc * 8));
                const float4 x1 = __ldg((const float4*)(g_xwm + (size_t)snd[i] * 64 + tc * 8 + 4));
                float2 p0 = up2(acc[i][0]), p1 = up2(acc[i][1]);
                float2 p2 = up2(acc[i][2]), p3 = up2(acc[i][3]);
                float v[8];
                v[0] = p0.x + x0.x + bA.x; v[1] = p0.y + x0.y + bA.y;
                v[2] = p1.x + x0.z + bA.z; v[3] = p1.y + x0.w + bA.w;
                v[4] = p2.x + x1.x + bB.x; v[5] = p2.y + x1.y + bB.y;
                v[6] = p3.x + x1.z + bB.z; v[7] = p3.y + x1.w + bB.w;
                *(float4*)(g_h1 + (size_t)n * 64 + tc * 8)     = make_float4(v[0], v[1], v[2], v[3]);
                *(float4*)(g_h1 + (size_t)n * 64 + tc * 8 + 4) = make_float4(v[4], v[5], v[6], v[7]);
#pragma unroll
                for (int j = 0; j < 8; ++j) { s_[j] += v[j]; q_[j] += v[j] * v[j]; }
                if (tc == 0) atomicAdd(&g_cnt[rec[i]], 1.0f);
            }
        }
        __syncthreads();
        buf ^= 1;
    }
    // one stats reduction per block
#pragma unroll
    for (int j = 0; j < 8; ++j) {
        s_[j] += __shfl_xor_sync(0xffffffffu, s_[j], 8);
        s_[j] += __shfl_xor_sync(0xffffffffu, s_[j], 16);
        q_[j] += __shfl_xor_sync(0xffffffffu, q_[j], 8);
        q_[j] += __shfl_xor_sync(0xffffffffu, q_[j], 16);
    }
    __syncthreads();
    if (tid < 128) A_s[0][tid] = 0.f;
    __syncthreads();
    if ((tid & 31) < 8) {
#pragma unroll
        for (int j = 0; j < 8; ++j) {
            atomicAdd(&A_s[0][tc * 8 + j], s_[j]);
            atomicAdd(&A_s[0][64 + tc * 8 + j], q_[j]);
        }
    }
    __syncthreads();
    if (tid < 64) {
        atomicAdd(&g_stat[0][tid], A_s[0][tid]);
        atomicAdd(&g_stat[1][tid], A_s[0][64 + tid]);
    }
}

__global__ void k_bnfin(const float* __restrict__ gamma,
                        const float* __restrict__ beta, float invcnt, int stage) {
    const int c = threadIdx.x;
    const float mu = g_stat[stage * 4 + 0][c] * invcnt;
    const float var = g_stat[stage * 4 + 1][c] * invcnt - mu * mu;
    const float sc = __ldg(gamma + c) * rsqrtf(var + 1e-5f);
    g_stat[stage * 4 + 2][c] = sc;
    g_stat[stage * 4 + 3][c] = __ldg(beta + c) - mu * sc;
}

// Persistent: m = relu(bn(h1)) @ w2m + b2m -> red.v4 scatter into g_agg.
__global__ __launch_bounds__(256, 2)
void k_edge2(const int* __restrict__ eidx, const float* __restrict__ Wg,
             const float* __restrict__ bias, int E, int ntiles) {
    __shared__ __align__(16) float A_s[2][128 * 64];
    __shared__ __align__(16) float W_s[64 * 64];
    const int tid = threadIdx.x;
    const int tc = tid & 7, tr = tid >> 3;
    const int c4 = tid & 15, rb = tid >> 4;
    fill_W(W_s, Wg, tid);
    const float4 bA = __ldg((const float4*)(bias + tc * 8));
    const float4 bB = __ldg((const float4*)(bias + tc * 8 + 4));
    const float4 scT = *(const float4*)(&g_stat[2][c4 * 4]);
    const float4 shT = *(const float4*)(&g_stat[3][c4 * 4]);

    int t = blockIdx.x;
    if (t < ntiles) {
        const int r0 = t * 128;
#pragma unroll
        for (int it = 0; it < 8; ++it) {
            const int r = rb + it * 16, e = r0 + r;
            cp16(A_s[0] + r * 64 + ((c4 ^ (r & 3)) << 2),
                 g_h1 + (size_t)e * 64 + c4 * 4, e < E ? 16 : 0);
        }
    }
    CP_COMMIT();
    int buf = 0;
    for (; t < ntiles; t += gridDim.x) {
        const int tn = t + gridDim.x;
        if (tn < ntiles) {
            const int r0n = tn * 128;
#pragma unroll
            for (int it = 0; it < 8; ++it) {
                const int r = rb + it * 16, e = r0n + r;
                cp16(A_s[buf ^ 1] + r * 64 + ((c4 ^ (r & 3)) << 2),
                     g_h1 + (size_t)e * 64 + c4 * 4, e < E ? 16 : 0);
            }
        }
        CP_COMMIT();
        const int r0 = t * 128;
        int rec[4];
#pragma unroll
        for (int i = 0; i < 4; ++i) {
            const int n = r0 + i * 32 + tr;
            rec[i] = (n < E) ? __ldg(eidx + E + n) : 0;
        }
        CP_WAIT1();
        __syncthreads();
        // in-place BN + ReLU on the smem tile
#pragma unroll
        for (int it = 0; it < 8; ++it) {
            const int r = rb + it * 16;
            float4* p = (float4*)(A_s[buf] + r * 64 + ((c4 ^ (r & 3)) << 2));
            float4 v = *p;
            v.x = fmaxf(fmaf(v.x, scT.x, shT.x), 0.f);
            v.y = fmaxf(fmaf(v.y, scT.y, shT.y), 0.f);
            v.z = fmaxf(fmaf(v.z, scT.z, shT.z), 0.f);
            v.w = fmaxf(fmaf(v.w, scT.w, shT.w), 0.f);
            *p = v;
        }
        __syncthreads();
        unsigned long long acc[4][4] = {};
        gemm_core(A_s[buf], W_s, acc, tr, tc);
#pragma unroll
        for (int i = 0; i < 4; ++i) {
            const int n = r0 + i * 32 + tr;
            if (n < E) {
                float2 p0 = up2(acc[i][0]), p1 = up2(acc[i][1]);
                float2 p2 = up2(acc[i][2]), p3 = up2(acc[i][3]);
                const float v0 = p0.x + bA.x, v1 = p0.y + bA.y;
                const float v2 = p1.x + bA.z, v3 = p1.y + bA.w;
                const float v4 = p2.x + bB.x, v5 = p2.y + bB.y;
                const float v6 = p3.x + bB.z, v7 = p3.y + bB.w;
                float* p = g_agg + (size_t)rec[i] * 64 + tc * 8;
                asm volatile("red.global.add.v4.f32 [%0], {%1,%2,%3,%4};"
                             :: "l"(p), "f"(v0), "f"(v1), "f"(v2), "f"(v3));
                asm volatile("red.global.add.v4.f32 [%0], {%1,%2,%3,%4};"
                             :: "l"(p + 4), "f"(v4), "f"(v5), "f"(v6), "f"(v7));
            }
        }
        __syncthreads();
        buf ^= 1;
    }
}

// Node stage 1: h1n[n] = (agg[n]/max(cnt,1))@Wbot + xwn[n] + b, BN stats.
__global__ __launch_bounds__(256, 2)
void k_node1(const float* __restrict__ Wbot, const float* __restrict__ bias,
             int nrows) {
    __shared__ __align__(16) float A_s[128 * 64];
    __shared__ __align__(16) float W_s[64 * 64];
    const int tid = threadIdx.x, r0 = blockIdx.x * 128;
    fill_W(W_s, Wbot, tid);
    {
        const int c4 = tid & 15, rb = tid >> 4;
#pragma unroll
        for (int it = 0; it < 8; ++it) {
            const int r = rb + it * 16, n = r0 + r;
            float4 v = make_float4(0.f, 0.f, 0.f, 0.f);
            if (n < nrows) {
                const float is = 1.0f / fmaxf(g_cnt[n], 1.0f);
                v = *(const float4*)(g_agg + (size_t)n * 64 + c4 * 4);
                v.x *= is; v.y *= is; v.z *= is; v.w *= is;
            }
            *(float4*)(A_s + r * 64 + ((c4 ^ (r & 3)) << 2)) = v;
        }
    }
    __syncthreads();
    const int tc = tid & 7, tr = tid >> 3;
    unsigned long long acc[4][4] = {};
    gemm_core(A_s, W_s, acc, tr, tc);
    const float4 bA = __ldg((const float4*)(bias + tc * 8));
    const float4 bB = __ldg((const float4*)(bias + tc * 8 + 4));
    float s_[8] = {}, q_[8] = {};
#pragma unroll
    for (int i = 0; i < 4; ++i) {
        const int n = r0 + i * 32 + tr;
        if (n < nrows) {
            const float4 x0 = __ldg((const float4*)(g_xwn + (size_t)n * 64 + tc * 8));
            const float4 x1 = __ldg((const float4*)(g_xwn + (size_t)n * 64 + tc * 8 + 4));
            float2 p0 = up2(acc[i][0]), p1 = up2(acc[i][1]);
            float2 p2 = up2(acc[i][2]), p3 = up2(acc[i][3]);
            float v[8];
            v[0] = p0.x + x0.x + bA.x; v[1] = p0.y + x0.y + bA.y;
            v[2] = p1.x + x0.z + bA.z; v[3] = p1.y + x0.w + bA.w;
            v[4] = p2.x + x1.x + bB.x; v[5] = p2.y + x1.y + bB.y;
            v[6] = p3.x + x1.z + bB.z; v[7] = p3.y + x1.w + bB.w;
            *(float4*)(g_h1n + (size_t)n * 64 + tc * 8)     = make_float4(v[0], v[1], v[2], v[3]);
            *(float4*)(g_h1n + (size_t)n * 64 + tc * 8 + 4) = make_float4(v[4], v[5], v[6], v[7]);
#pragma unroll
            for (int j = 0; j < 8; ++j) { s_[j] += v[j]; q_[j] += v[j] * v[j]; }
        }
    }
#pragma unroll
    for (int j = 0; j < 8; ++j) {
        s_[j] += __shfl_xor_sync(0xffffffffu, s_[j], 8);
        s_[j] += __shfl_xor_sync(0xffffffffu, s_[j], 16);
        q_[j] += __shfl_xor_sync(0xffffffffu, q_[j], 8);
        q_[j] += __shfl_xor_sync(0xffffffffu, q_[j], 16);
    }
    __syncthreads();
    if (tid < 128) A_s[tid] = 0.f;
    __syncthreads();
    if ((tid & 31) < 8) {
#pragma unroll
        for (int j = 0; j < 8; ++j) {
            atomicAdd(&A_s[tc * 8 + j], s_[j]);
            atomicAdd(&A_s[64 + tc * 8 + j], q_[j]);
        }
    }
    __syncthreads();
    if (tid < 64) {
        atomicAdd(&g_stat[4][tid], A_s[tid]);
        atomicAdd(&g_stat[5][tid], A_s[64 + tid]);
    }
}

// Node stage 2: out = relu(bn(h1n)) @ w2n + b2n
__global__ __launch_bounds__(256, 2)
void k_node2(const float* __restrict__ Wg, const float* __restrict__ bias,
             int nrows, float* __restrict__ out) {
    __shared__ __align__(16) float A_s[128 * 64];
    __shared__ __align__(16) float W_s[64 * 64];
    const int tid = threadIdx.x, r0 = blockIdx.x * 128;
    fill_W(W_s, Wg, tid);
    {
        const int c4 = tid & 15, rb = tid >> 4;
        const float4 sc = *(const float4*)(&g_stat[6][c4 * 4]);
        const float4 sh = *(const float4*)(&g_stat[7][c4 * 4]);
#pragma unroll
        for (int it = 0; it < 8; ++it) {
            const int r = rb + it * 16, n = r0 + r;
            float4 v = make_float4(0.f, 0.f, 0.f, 0.f);
            if (n < nrows) {
                v = *(const float4*)(g_h1n + (size_t)n * 64 + c4 * 4);
                v.x = fmaxf(fmaf(v.x, sc.x, sh.x), 0.f);
                v.y = fmaxf(fmaf(v.y, sc.y, sh.y), 0.f);
                v.z = fmaxf(fmaf(v.z, sc.z, sh.z), 0.f);
                v.w = fmaxf(fmaf(v.w, sc.w, sh.w), 0.f);
            }
            *(float4*)(A_s + r * 64 + ((c4 ^ (r & 3)) << 2)) = v;
        }
    }
    __syncthreads();
    const int tc = tid & 7, tr = tid >> 3;
    unsigned long long acc[4][4] = {};
    gemm_core(A_s, W_s, acc, tr, tc);
    const float4 bA = __ldg((const float4*)(bias + tc * 8));
    const float4 bB = __ldg((const float4*)(bias + tc * 8 + 4));
#pragma unroll
    for (int i = 0; i < 4; ++i) {
        const int n = r0 + i * 32 + tr;
        if (n < nrows) {
            float2 p0 = up2(acc[i][0]), p1 = up2(acc[i][1]);
            float2 p2 = up2(acc[i][2]), p3 = up2(acc[i][3]);
            *(float4*)(out + (size_t)n * 64 + tc * 8) =
                make_float4(p0.x + bA.x, p0.y + bA.y, p1.x + bA.z, p1.y + bA.w);
            *(float4*)(out + (size_t)n * 64 + tc * 8 + 4) =
                make_float4(p2.x + bB.x, p2.y + bB.y, p3.x + bB.z, p3.y + bB.w);
        }
    }
}

extern "C" void kernel_launch(void* const* d_in, const int* in_sizes, int n_in,
                              void* d_out, int out_size) {
    const float* x    = (const float*)d_in[0];
    const int*   eidx = (const int*)  d_in[1];
    const float* ea   = (const float*)d_in[2];
    const float* w1m  = (const float*)d_in[5];
    const float* b1m  = (const float*)d_in[6];
    const float* gm   = (const float*)d_in[7];
    const float* bm   = (const float*)d_in[8];
    const float* w2m  = (const float*)d_in[9];
    const float* b2m  = (const float*)d_in[10];
    const float* w1n  = (const float*)d_in[11];
    const float* b1n  = (const float*)d_in[12];
    const float* gn   = (const float*)d_in[13];
    const float* bn   = (const float*)d_in[14];
    const float* w2n  = (const float*)d_in[15];
    const float* b2n  = (const float*)d_in[16];
    const int N = in_sizes[0] / 64;
    const int E = in_sizes[2] / 64;
    const int gN = (N + 127) / 128, gE = (E + 127) / 128;
    const int PERS = 296;  // 2 blocks per SM x 148 SMs

    k_zero<<<(N * 64 + 255) / 256, 256>>>(N * 64, N);
    k_rowgemm<<<dim3(gN, 2), 256>>>(x, w1m, w1n, N);
    k_edge1<<<PERS, 256>>>(ea, eidx, w1m + 4096, b1m, E, gE);
    k_bnfin<<<1, 64>>>(gm, bm, 1.0f / (float)E, 0);
    k_edge2<<<PERS, 256>>>(eidx, w2m, b2m, E, gE);
    k_node1<<<gN, 256>>>(w1n + 4096, b1n, N);
    k_bnfin<<<1, 64>>>(gn, bn, 1.0f / (float)N, 1);
    k_node2<<<gN, 256>>>(w2n, b2n, N, (float*)d_out);
}

// round 11
// speedup vs baseline: 1.2030x; 1.0406x over previous
#include <cuda_runtime.h>
#include <cuda_bf16.h>

// NodeModel GNN: two (Linear -> BN(train) -> ReLU -> Linear) stages with a
// scatter-mean between them. N=50000, E=800000, FX=H=64.
// Concat-GEMMs split:  [x[s],ea]@W = (x@W_top)[s] + ea@W_bot.
// Edge kernels persistent (2/SM), cp.async double-buffered; h1 kept in bf16
// (BN stats accumulated in fp32 before rounding).

static __device__ __nv_bfloat16 g_h1[800000 * 64];  // edge hidden (pre-BN, bf16)
static __device__ float g_h1n[ 50048 * 64];
static __device__ float g_xwm[ 50048 * 64];
static __device__ float g_xwn[ 50048 * 64];
static __device__ float g_agg[ 50048 * 64];
static __device__ float g_cnt[ 50048];
static __device__ float g_stat[8][64];              // {sum,ssq,scale,shift} x {m,n}

__device__ __forceinline__ float2 up2(unsigned long long p) {
    float2 r;
    asm("mov.b64 {%0, %1}, %2;" : "=f"(r.x), "=f"(r.y) : "l"(p));
    return r;
}
__device__ __forceinline__ unsigned long long dup2(float a) {
    unsigned long long r; unsigned int u = __float_as_uint(a);
    asm("mov.b64 %0, {%1, %1};" : "=l"(r) : "r"(u));
    return r;
}
#define FMA2(acc, a, w) \
    asm("fma.rn.f32x2 %0, %1, %2, %0;" : "+l"(acc) : "l"(a), "l"(w))

// pack {lo=a, hi=b} as bf16x2
__device__ __forceinline__ unsigned pkbf(float a, float b) {
    unsigned r;
    asm("cvt.rn.bf16x2.f32 %0, %1, %2;" : "=r"(r) : "f"(b), "f"(a));
    return r;
}

__device__ __forceinline__ void cp16(void* dst, const void* src, int sz) {
    unsigned d = (unsigned)__cvta_generic_to_shared(dst);
    asm volatile("cp.async.cg.shared.global [%0], [%1], 16, %2;"
                 :: "r"(d), "l"(src), "r"(sz));
}
#define CP_COMMIT() asm volatile("cp.async.commit_group;")
#define CP_WAIT1()  asm volatile("cp.async.wait_group 1;")

__device__ __forceinline__ void fill_W(float* Ws, const float* __restrict__ Wg,
                                       int tid) {
#pragma unroll
    for (int it = 0; it < 16; ++it) Ws[tid + it * 256] = __ldg(Wg + tid + it * 256);
}

// C[128x64] = A[128x64] @ W[64x64]; A XOR-swizzled at float4 granularity.
__device__ __forceinline__ void gemm_core(const float* __restrict__ A_s,
                                          const float* __restrict__ W_s,
                                          unsigned long long acc[4][4],
                                          int tr, int tc) {
#pragma unroll
    for (int k4 = 0; k4 < 16; ++k4) {
        float4 a[4];
#pragma unroll
        for (int i = 0; i < 4; ++i) {
            const int r = i * 32 + tr;
            a[i] = *(const float4*)(A_s + r * 64 + ((k4 ^ (r & 3)) << 2));
        }
#pragma unroll
        for (int kk = 0; kk < 4; ++kk) {
            const int k = k4 * 4 + kk;
            const ulonglong2 w0 = *(const ulonglong2*)(W_s + k * 64 + tc * 8);
            const ulonglong2 w1 = *(const ulonglong2*)(W_s + k * 64 + tc * 8 + 4);
#pragma unroll
            for (int i = 0; i < 4; ++i) {
                const unsigned long long a2 = dup2(((const float*)&a[i])[kk]);
                FMA2(acc[i][0], a2, w0.x);
                FMA2(acc[i][1], a2, w0.y);
                FMA2(acc[i][2], a2, w1.x);
                FMA2(acc[i][3], a2, w1.y);
            }
        }
    }
}

__global__ void k_zero(int n64, int n) {
    const int i = blockIdx.x * 256 + threadIdx.x;
    if (i < n64) g_agg[i] = 0.f;
    if (i < n)   g_cnt[i] = 0.f;
    if (i < 512) ((float*)g_stat)[i] = 0.f;
}

// xw = X @ W_top; blockIdx.y selects (w1m -> g_xwm) / (w1n -> g_xwn)
__global__ __launch_bounds__(256, 2)
void k_rowgemm(const float* __restrict__ X, const float* __restrict__ Wm,
               const float* __restrict__ Wn, int nrows) {
    __shared__ __align__(16) float A_s[128 * 64];
    __shared__ __align__(16) float W_s[64 * 64];
    const int tid = threadIdx.x, r0 = blockIdx.x * 128;
    fill_W(W_s, blockIdx.y ? Wn : Wm, tid);
    {
        const int c4 = tid & 15, rb = tid >> 4;
#pragma unroll
        for (int it = 0; it < 8; ++it) {
            const int r = rb + it * 16, n = r0 + r;
            float4 v = make_float4(0.f, 0.f, 0.f, 0.f);
            if (n < nrows) v = __ldg((const float4*)(X + (size_t)n * 64 + c4 * 4));
            *(float4*)(A_s + r * 64 + ((c4 ^ (r & 3)) << 2)) = v;
        }
    }
    __syncthreads();
    const int tc = tid & 7, tr = tid >> 3;
    unsigned long long acc[4][4] = {};
    gemm_core(A_s, W_s, acc, tr, tc);
    float* outp = blockIdx.y ? g_xwn : g_xwm;
#pragma unroll
    for (int i = 0; i < 4; ++i) {
        const int n = r0 + i * 32 + tr;
        if (n < nrows) {
            float2 p0 = up2(acc[i][0]), p1 = up2(acc[i][1]);
            float2 p2 = up2(acc[i][2]), p3 = up2(acc[i][3]);
            *(float4*)(outp + (size_t)n * 64 + tc * 8)     = make_float4(p0.x, p0.y, p1.x, p1.y);
            *(float4*)(outp + (size_t)n * 64 + tc * 8 + 4) = make_float4(p2.x, p2.y, p3.x, p3.y);
        }
    }
}

// Persistent: h1[e] = ea[e]@Wbot + xwm[send[e]] + b -> bf16, BN stats, counts.
__global__ __launch_bounds__(256, 2)
void k_edge1(const float* __restrict__ ea, const int* __restrict__ eidx,
             const float* __restrict__ Wbot, const float* __restrict__ bias,
             int E, int ntiles) {
    __shared__ __align__(16) float A_s[2][128 * 64];
    __shared__ __align__(16) float W_s[64 * 64];
    const int tid = threadIdx.x;
    const int tc = tid & 7, tr = tid >> 3;
    const int c4 = tid & 15, rb = tid >> 4;
    fill_W(W_s, Wbot, tid);
    const float4 bA = __ldg((const float4*)(bias + tc * 8));
    const float4 bB = __ldg((const float4*)(bias + tc * 8 + 4));
    float s_[8] = {}, q_[8] = {};

    int t = blockIdx.x;
    if (t < ntiles) {
        const int r0 = t * 128;
#pragma unroll
        for (int it = 0; it < 8; ++it) {
            const int r = rb + it * 16, e = r0 + r;
            cp16(A_s[0] + r * 64 + ((c4 ^ (r & 3)) << 2),
                 ea + (size_t)e * 64 + c4 * 4, e < E ? 16 : 0);
        }
    }
    CP_COMMIT();
    int buf = 0;
    for (; t < ntiles; t += gridDim.x) {
        const int tn = t + gridDim.x;
        if (tn < ntiles) {
            const int r0n = tn * 128;
#pragma unroll
            for (int it = 0; it < 8; ++it) {
                const int r = rb + it * 16, e = r0n + r;
                cp16(A_s[buf ^ 1] + r * 64 + ((c4 ^ (r & 3)) << 2),
                     ea + (size_t)e * 64 + c4 * 4, e < E ? 16 : 0);
            }
        }
        CP_COMMIT();
        const int r0 = t * 128;
        int snd[4], rec[4];
        float4 x0[4];
#pragma unroll
        for (int i = 0; i < 4; ++i) {
            const int n = r0 + i * 32 + tr;
            snd[i] = (n < E) ? __ldg(eidx + n) : 0;
            rec[i] = (n < E) ? __ldg(eidx + E + n) : 0;
        }
#pragma unroll
        for (int i = 0; i < 4; ++i)       // prefetch gathers behind the GEMM
            x0[i] = __ldg((const float4*)(g_xwm + (size_t)snd[i] * 64 + tc * 8));
        CP_WAIT1();
        __syncthreads();
        unsigned long long acc[4][4] = {};
        gemm_core(A_s[buf], W_s, acc, tr, tc);
        float4 x1[4];
#pragma unroll
        for (int i = 0; i < 4; ++i)
            x1[i] = __ldg((const float4*)(g_xwm + (size_t)snd[i] * 64 + tc * 8 + 4));
#pragma unroll
        for (int i = 0; i < 4; ++i) {
            const int n = r0 + i * 32 + tr;
            if (n < E) {
                float2 p0 = up2(acc[i][0]), p1 = up2(acc[i][1]);
                float2 p2 = up2(acc[i][2]), p3 = up2(acc[i][3]);
                float v[8];
                v[0] = p0.x + x0[i].x + bA.x; v[1] = p0.y + x0[i].y + bA.y;
                v[2] = p1.x + x0[i].z + bA.z; v[3] = p1.y + x0[i].w + bA.w;
                v[4] = p2.x + x1[i].x + bB.x; v[5] = p2.y + x1[i].y + bB.y;
                v[6] = p3.x + x1[i].z + bB.z; v[7] = p3.y + x1[i].w + bB.w;
                *(uint4*)(g_h1 + (size_t)n * 64 + tc * 8) =
                    make_uint4(pkbf(v[0], v[1]), pkbf(v[2], v[3]),
                               pkbf(v[4], v[5]), pkbf(v[6], v[7]));
#pragma unroll
                for (int j = 0; j < 8; ++j) { s_[j] += v[j]; q_[j] += v[j] * v[j]; }
                if (tc == 0) atomicAdd(&g_cnt[rec[i]], 1.0f);
            }
        }
        __syncthreads();
        buf ^= 1;
    }
#pragma unroll
    for (int j = 0; j < 8; ++j) {
        s_[j] += __shfl_xor_sync(0xffffffffu, s_[j], 8);
        s_[j] += __shfl_xor_sync(0xffffffffu, s_[j], 16);
        q_[j] += __shfl_xor_sync(0xffffffffu, q_[j], 8);
        q_[j] += __shfl_xor_sync(0xffffffffu, q_[j], 16);
    }
    __syncthreads();
    if (tid < 128) A_s[0][tid] = 0.f;
    __syncthreads();
    if ((tid & 31) < 8) {
#pragma unroll
        for (int j = 0; j < 8; ++j) {
            atomicAdd(&A_s[0][tc * 8 + j], s_[j]);
            atomicAdd(&A_s[0][64 + tc * 8 + j], q_[j]);
        }
    }
    __syncthreads();
    if (tid < 64) {
        atomicAdd(&g_stat[0][tid], A_s[0][tid]);
        atomicAdd(&g_stat[1][tid], A_s[0][64 + tid]);
    }
}

__global__ void k_bnfin(const float* __restrict__ gamma,
                        const float* __restrict__ beta, float invcnt, int stage) {
    const int c = threadIdx.x;
    const float mu = g_stat[stage * 4 + 0][c] * invcnt;
    const float var = g_stat[stage * 4 + 1][c] * invcnt - mu * mu;
    const float sc = __ldg(gamma + c) * rsqrtf(var + 1e-5f);
    g_stat[stage * 4 + 2][c] = sc;
    g_stat[stage * 4 + 3][c] = __ldg(beta + c) - mu * sc;
}

// Persistent: m = relu(bn(h1_bf16)) @ w2m + b2m -> red.v4 scatter into g_agg.
__global__ __launch_bounds__(256, 2)
void k_edge2(const int* __restrict__ eidx, const float* __restrict__ Wg,
             const float* __restrict__ bias, int E, int ntiles) {
    __shared__ __align__(16) __nv_bfloat16 S_s[2][128 * 64];  // 2 x 16KB staging
    __shared__ __align__(16) float A_s[128 * 64];             // 32KB compute
    __shared__ __align__(16) float W_s[64 * 64];              // 16KB
    const int tid = threadIdx.x;
    const int tc = tid & 7, tr = tid >> 3;   // tr in 0..31
    fill_W(W_s, Wg, tid);
    const float4 bA = __ldg((const float4*)(bias + tc * 8));
    const float4 bB = __ldg((const float4*)(bias + tc * 8 + 4));
    const float4 scA = *(const float4*)(&g_stat[2][tc * 8]);
    const float4 scB = *(const float4*)(&g_stat[2][tc * 8 + 4]);
    const float4 shA = *(const float4*)(&g_stat[3][tc * 8]);
    const float4 shB = *(const float4*)(&g_stat[3][tc * 8 + 4]);

    int t = blockIdx.x;
    if (t < ntiles) {
        const int r0 = t * 128;
#pragma unroll
        for (int it = 0; it < 4; ++it) {
            const int r = tr + it * 32, e = r0 + r;
            cp16(S_s[0] + r * 64 + tc * 8,
                 g_h1 + (size_t)e * 64 + tc * 8, e < E ? 16 : 0);
        }
    }
    CP_COMMIT();
    int buf = 0;
    for (; t < ntiles; t += gridDim.x) {
        const int tn = t + gridDim.x;
        if (tn < ntiles) {
            const int r0n = tn * 128;
#pragma unroll
            for (int it = 0; it < 4; ++it) {
                const int r = tr + it * 32, e = r0n + r;
                cp16(S_s[buf ^ 1] + r * 64 + tc * 8,
                     g_h1 + (size_t)e * 64 + tc * 8, e < E ? 16 : 0);
            }
        }
        CP_COMMIT();
        const int r0 = t * 128;
        int rec[4];
#pragma unroll
        for (int i = 0; i < 4; ++i) {
            const int n = r0 + i * 32 + tr;
            rec[i] = (n < E) ? __ldg(eidx + E + n) : 0;
        }
        CP_WAIT1();
        __syncthreads();
        // pre-pass: bf16 -> fp32, BN + ReLU, swizzled write into A_s
#pragma unroll
        for (int it = 0; it < 4; ++it) {
            const int r = tr + it * 32;
            uint4 u = *(const uint4*)(S_s[buf] + r * 64 + tc * 8);
            const __nv_bfloat162* hp = (const __nv_bfloat162*)&u;
            float2 f0 = __bfloat1622float2(hp[0]);
            float2 f1 = __bfloat1622float2(hp[1]);
            float2 f2 = __bfloat1622float2(hp[2]);
            float2 f3 = __bfloat1622float2(hp[3]);
            float4 w0, w1;
            w0.x = fmaxf(fmaf(f0.x, scA.x, shA.x), 0.f);
            w0.y = fmaxf(fmaf(f0.y, scA.y, shA.y), 0.f);
            w0.z = fmaxf(fmaf(f1.x, scA.z, shA.z), 0.f);
            w0.w = fmaxf(fmaf(f1.y, scA.w, shA.w), 0.f);
            w1.x = fmaxf(fmaf(f2.x, scB.x, shB.x), 0.f);
            w1.y = fmaxf(fmaf(f2.y, scB.y, shB.y), 0.f);
            w1.z = fmaxf(fmaf(f3.x, scB.z, shB.z), 0.f);
            w1.w = fmaxf(fmaf(f3.y, scB.w, shB.w), 0.f);
            *(float4*)(A_s + r * 64 + (((2 * tc)     ^ (r & 3)) << 2)) = w0;
            *(float4*)(A_s + r * 64 + (((2 * tc + 1) ^ (r & 3)) << 2)) = w1;
        }
        __syncthreads();
        unsigned long long acc[4][4] = {};
        gemm_core(A_s, W_s, acc, tr, tc);
#pragma unroll
        for (int i = 0; i < 4; ++i) {
            const int n = r0 + i * 32 + tr;
            if (n < E) {
                float2 p0 = up2(acc[i][0]), p1 = up2(acc[i][1]);
                float2 p2 = up2(acc[i][2]), p3 = up2(acc[i][3]);
                const float v0 = p0.x + bA.x, v1 = p0.y + bA.y;
                const float v2 = p1.x + bA.z, v3 = p1.y + bA.w;
                const float v4 = p2.x + bB.x, v5 = p2.y + bB.y;
                const float v6 = p3.x + bB.z, v7 = p3.y + bB.w;
                float* p = g_agg + (size_t)rec[i] * 64 + tc * 8;
                asm volatile("red.global.add.v4.f32 [%0], {%1,%2,%3,%4};"
                             :: "l"(p), "f"(v0), "f"(v1), "f"(v2), "f"(v3));
                asm volatile("red.global.add.v4.f32 [%0], {%1,%2,%3,%4};"
                             :: "l"(p + 4), "f"(v4), "f"(v5), "f"(v6), "f"(v7));
            }
        }
        __syncthreads();
        buf ^= 1;
    }
}

// Node stage 1: h1n[n] = (agg[n]/max(cnt,1))@Wbot + xwn[n] + b, BN stats.
__global__ __launch_bounds__(256, 2)
void k_node1(const float* __restrict__ Wbot, const float* __restrict__ bias,
             int nrows) {
    __shared__ __align__(16) float A_s[128 * 64];
    __shared__ __align__(16) float W_s[64 * 64];
    const int tid = threadIdx.x, r0 = blockIdx.x * 128;
    fill_W(W_s, Wbot, tid);
    {
        const int c4 = tid & 15, rb = tid >> 4;
#pragma unroll
        for (int it = 0; it < 8; ++it) {
            const int r = rb + it * 16, n = r0 + r;
            float4 v = make_float4(0.f, 0.f, 0.f, 0.f);
            if (n < nrows) {
                const float is = 1.0f / fmaxf(g_cnt[n], 1.0f);
                v = *(const float4*)(g_agg + (size_t)n * 64 + c4 * 4);
                v.x *= is; v.y *= is; v.z *= is; v.w *= is;
            }
            *(float4*)(A_s + r * 64 + ((c4 ^ (r & 3)) << 2)) = v;
        }
    }
    __syncthreads();
    const int tc = tid & 7, tr = tid >> 3;
    unsigned long long acc[4][4] = {};
    gemm_core(A_s, W_s, acc, tr, tc);
    const float4 bA = __ldg((const float4*)(bias + tc * 8));
    const float4 bB = __ldg((const float4*)(bias + tc * 8 + 4));
    float s_[8] = {}, q_[8] = {};
#pragma unroll
    for (int i = 0; i < 4; ++i) {
        const int n = r0 + i * 32 + tr;
        if (n < nrows) {
            const float4 x0 = __ldg((const float4*)(g_xwn + (size_t)n * 64 + tc * 8));
            const float4 x1 = __ldg((const float4*)(g_xwn + (size_t)n * 64 + tc * 8 + 4));
            float2 p0 = up2(acc[i][0]), p1 = up2(acc[i][1]);
            float2 p2 = up2(acc[i][2]), p3 = up2(acc[i][3]);
            float v[8];
            v[0] = p0.x + x0.x + bA.x; v[1] = p0.y + x0.y + bA.y;
            v[2] = p1.x + x0.z + bA.z; v[3] = p1.y + x0.w + bA.w;
            v[4] = p2.x + x1.x + bB.x; v[5] = p2.y + x1.y + bB.y;
            v[6] = p3.x + x1.z + bB.z; v[7] = p3.y + x1.w + bB.w;
            *(float4*)(g_h1n + (size_t)n * 64 + tc * 8)     = make_float4(v[0], v[1], v[2], v[3]);
            *(float4*)(g_h1n + (size_t)n * 64 + tc * 8 + 4) = make_float4(v[4], v[5], v[6], v[7]);
#pragma unroll
            for (int j = 0; j < 8; ++j) { s_[j] += v[j]; q_[j] += v[j] * v[j]; }
        }
    }
#pragma unroll
    for (int j = 0; j < 8; ++j) {
        s_[j] += __shfl_xor_sync(0xffffffffu, s_[j], 8);
        s_[j] += __shfl_xor_sync(0xffffffffu, s_[j], 16);
        q_[j] += __shfl_xor_sync(0xffffffffu, q_[j], 8);
        q_[j] += __shfl_xor_sync(0xffffffffu, q_[j], 16);
    }
    __syncthreads();
    if (tid < 128) A_s[tid] = 0.f;
    __syncthreads();
    if ((tid & 31) < 8) {
#pragma unroll
        for (int j = 0; j < 8; ++j) {
            atomicAdd(&A_s[tc * 8 + j], s_[j]);
            atomicAdd(&A_s[64 + tc * 8 + j], q_[j]);
        }
    }
    __syncthreads();
    if (tid < 64) {
        atomicAdd(&g_stat[4][tid], A_s[tid]);
        atomicAdd(&g_stat[5][tid], A_s[64 + tid]);
    }
}

// Node stage 2: out = relu(bn(h1n)) @ w2n + b2n
__global__ __launch_bounds__(256, 2)
void k_node2(const float* __restrict__ Wg, const float* __restrict__ bias,
             int nrows, float* __restrict__ out) {
    __shared__ __align__(16) float A_s[128 * 64];
    __shared__ __align__(16) float W_s[64 * 64];
    const int tid = threadIdx.x, r0 = blockIdx.x * 128;
    fill_W(W_s, Wg, tid);
    {
        const int c4 = tid & 15, rb = tid >> 4;
        const float4 sc = *(const float4*)(&g_stat[6][c4 * 4]);
        const float4 sh = *(const float4*)(&g_stat[7][c4 * 4]);
#pragma unroll
        for (int it = 0; it < 8; ++it) {
            const int r = rb + it * 16, n = r0 + r;
            float4 v = make_float4(0.f, 0.f, 0.f, 0.f);
            if (n < nrows) {
                v = *(const float4*)(g_h1n + (size_t)n * 64 + c4 * 4);
                v.x = fmaxf(fmaf(v.x, sc.x, sh.x), 0.f);
                v.y = fmaxf(fmaf(v.y, sc.y, sh.y), 0.f);
                v.z = fmaxf(fmaf(v.z, sc.z, sh.z), 0.f);
                v.w = fmaxf(fmaf(v.w, sc.w, sh.w), 0.f);
            }
            *(float4*)(A_s + r * 64 + ((c4 ^ (r & 3)) << 2)) = v;
        }
    }
    __syncthreads();
    const int tc = tid & 7, tr = tid >> 3;
    unsigned long long acc[4][4] = {};
    gemm_core(A_s, W_s, acc, tr, tc);
    const float4 bA = __ldg((const float4*)(bias + tc * 8));
    const float4 bB = __ldg((const float4*)(bias + tc * 8 + 4));
#pragma unroll
    for (int i = 0; i < 4; ++i) {
        const int n = r0 + i * 32 + tr;
        if (n < nrows) {
            float2 p0 = up2(acc[i][0]), p1 = up2(acc[i][1]);
            float2 p2 = up2(acc[i][2]), p3 = up2(acc[i][3]);
            *(float4*)(out + (size_t)n * 64 + tc * 8) =
                make_float4(p0.x + bA.x, p0.y + bA.y, p1.x + bA.z, p1.y + bA.w);
            *(float4*)(out + (size_t)n * 64 + tc * 8 + 4) =
                make_float4(p2.x + bB.x, p2.y + bB.y, p3.x + bB.z, p3.y + bB.w);
        }
    }
}

extern "C" void kernel_launch(void* const* d_in, const int* in_sizes, int n_in,
                              void* d_out, int out_size) {
    const float* x    = (const float*)d_in[0];
    const int*   eidx = (const int*)  d_in[1];
    const float* ea   = (const float*)d_in[2];
    const float* w1m  = (const float*)d_in[5];
    const float* b1m  = (const float*)d_in[6];
    const float* gm   = (const float*)d_in[7];
    const float* bm   = (const float*)d_in[8];
    const float* w2m  = (const float*)d_in[9];
    const float* b2m  = (const float*)d_in[10];
    const float* w1n  = (const float*)d_in[11];
    const float* b1n  = (const float*)d_in[12];
    const float* gn   = (const float*)d_in[13];
    const float* bn   = (const float*)d_in[14];
    const float* w2n  = (const float*)d_in[15];
    const float* b2n  = (const float*)d_in[16];
    const int N = in_sizes[0] / 64;
    const int E = in_sizes[2] / 64;
    const int gN = (N + 127) / 128, gE = (E + 127) / 128;
    const int PERS = 296;  // 2 blocks per SM x 148 SMs

    k_zero<<<(N * 64 + 255) / 256, 256>>>(N * 64, N);
    k_rowgemm<<<dim3(gN, 2), 256>>>(x, w1m, w1n, N);
    k_edge1<<<PERS, 256>>>(ea, eidx, w1m + 4096, b1m, E, gE);
    k_bnfin<<<1, 64>>>(gm, bm, 1.0f / (float)E, 0);
    k_edge2<<<PERS, 256>>>(eidx, w2m, b2m, E, gE);
    k_node1<<<gN, 256>>>(w1n + 4096, b1n, N);
    k_bnfin<<<1, 64>>>(gn, bn, 1.0f / (float)N, 1);
    k_node2<<<gN, 256>>>(w2n, b2n, N, (float*)d_out);
}